// round 10
// baseline (speedup 1.0000x reference)
#include <cuda_runtime.h>
#include <cuda_fp16.h>

#define BN 64
#define RN 2048
#define CN 32
#define ON 32
#define INN 16
#define CO 1024      // CN*ON
#define CO4 256      // CO/4
#define COH 512      // CO/2 (half2 per (b,r) row)
#define COG 128      // CO/8 (16B granules of half per row)

#define K1_R 16      // r per k1 block
#define K1_NRT 128   // RN / K1_R
#define RT_RT 64     // r per route block
#define RT_NRT 32    // RN / RT_RT
#define CH 8         // r per SMEM chunk in route
#define NCH 8        // chunks per route block

typedef unsigned long long u64;

// ---- scratch (device globals; allocation-free) ----
__device__ __half2 g_uhat[(size_t)BN * RN * COH];         // 256 MiB (fp16 u_hat)
__device__ float4 g_part0[(size_t)K1_NRT * BN * CO4];     // 32 MiB (s0 partials)
__device__ float4 g_part[(size_t)RT_NRT * BN * CO4];      // 8 MiB  (s1/s2 partials)
__device__ float  g_vsum[BN * CO];                        // running v0(+v1)

__device__ __forceinline__ u64 ffma2(u64 a, u64 b, u64 c) {
    u64 d;
    asm("fma.rn.f32x2 %0, %1, %2, %3;" : "=l"(d) : "l"(a), "l"(b), "l"(c));
    return d;
}
__device__ __forceinline__ float hsum2(u64 a) {
    float lo, hi;
    asm("mov.b64 {%0,%1}, %2;" : "=f"(lo), "=f"(hi) : "l"(a));
    return lo + hi;
}
// 16B-granule XOR swizzle (index form, route kernel)
__device__ __forceinline__ int swz(int g) {
    return (g & ~7) | ((g & 7) ^ ((g >> 3) & 7));
}
// k1 W-buffer swizzle: granule G -> BYTE offset. slot = (G&7)^((G>>3)&7):
// writes (consecutive G) and reads (G = 8*tc+j, j fixed, tc consecutive) conflict-free.
__device__ __forceinline__ int wswz2(int G) {
    return ((G >> 3) << 7) | (((G & 7) ^ ((G >> 3) & 7)) << 4);
}
__device__ __forceinline__ void cpa16(void* dst, const void* src) {
    unsigned d = (unsigned)__cvta_generic_to_shared(dst);
    asm volatile("cp.async.cg.shared.global [%0], [%1], 16;\n" ::"r"(d), "l"(src));
}
__device__ __forceinline__ void cpa_commit() {
    asm volatile("cp.async.commit_group;\n");
}
template <int N>
__device__ __forceinline__ void cpa_wait() {
    asm volatile("cp.async.wait_group %0;\n" ::"n"(N));
}
__device__ __forceinline__ void lds_v2u64(u64& a, u64& b, const void* p) {
    unsigned s = (unsigned)__cvta_generic_to_shared(p);
    asm volatile("ld.shared.v2.u64 {%0,%1}, [%2];" : "=l"(a), "=l"(b) : "r"(s));
}

// ================= K1: u_hat GEMM, register s0 partials =================
// grid (4, 128): x = co-quarter (256 co), y = r-tile (16 r). 512 threads:
// t = bg*128 + tc. bg = b-group (16 b), tc owns co pair (2tc, 2tc+1) in quarter.
// __launch_bounds__(512, 1): full 128-reg budget, NO spills (R9 lesson: plain
// (512) made ptxas pick 64 regs for 2 CTA/SM and spill s0/W to local).
__global__ void __launch_bounds__(512, 1) k1_uhat(const float* __restrict__ x,
                                                  const float* __restrict__ W) {
    __shared__ float wbuf[2][4096];   // 2 x 16 KB (256 co x 16 in, swizzled)
    __shared__ float xbuf[2][1024];   // 2 x 4 KB  (64 b x 16 in)

    const int quarter = blockIdx.x;
    const int rt      = blockIdx.y;
    const int t       = threadIdx.x;
    const int tc      = t & 127;   // co-pair index within quarter
    const int bg      = t >> 7;    // b-group (16 b each)
    const int bbase   = bg * 16;

    const float* Wbase = W + (size_t)rt * K1_R * CO * INN + (size_t)quarter * 256 * INN;
    const float* xbase = x + rt * K1_R * INN;

    auto stage = [&](int rr, int buf) {
        const float* wsrc = Wbase + (size_t)rr * CO * INN;
        #pragma unroll
        for (int k = 0; k < 2; k++) {
            const int G = t + 512 * k;   // 1024 granules = 16 KB
            cpa16((char*)wbuf[buf] + wswz2(G), wsrc + 4 * G);
        }
        if (t < 256) {
            const int b = t >> 2, q = t & 3;
            cpa16(&xbuf[buf][16 * b + 4 * q],
                  xbase + ((size_t)b * RN + rr) * INN + 4 * q);
        }
        cpa_commit();
    };

    stage(0, 0);

    // half2 destination: co pair (2tc) -> half2 index quarter*128 + tc
    __half2* uout = g_uhat + (size_t)(rt * K1_R) * COH + quarter * 128 + tc;

    float2 s0[16];
    #pragma unroll
    for (int i = 0; i < 16; i++) s0[i] = make_float2(0.f, 0.f);

    for (int rr = 0; rr < K1_R; rr++) {
        const int buf = rr & 1;
        cpa_wait<0>();
        __syncthreads();
        if (rr + 1 < K1_R) stage(rr + 1, buf ^ 1);

        // thread's two W rows: granules 8tc..8tc+7 (swizzled)
        u64 w[2][8];
        #pragma unroll
        for (int cc = 0; cc < 2; cc++)
            #pragma unroll
            for (int q = 0; q < 4; q++)
                lds_v2u64(w[cc][2 * q], w[cc][2 * q + 1],
                          (char*)wbuf[buf] + wswz2(8 * tc + 4 * cc + q));

        __half2* up = uout + (size_t)rr * COH;

        #pragma unroll 4
        for (int bi = 0; bi < 16; bi++) {
            const int b = bbase + bi;
            u64 xa[8];
            #pragma unroll
            for (int q = 0; q < 4; q++)
                lds_v2u64(xa[2 * q], xa[2 * q + 1], &xbuf[buf][16 * b + 4 * q]);

            u64 a0 = 0ull, a1 = 0ull;
            #pragma unroll
            for (int p = 0; p < 8; p++) {
                a0 = ffma2(w[0][p], xa[p], a0);
                a1 = ffma2(w[1][p], xa[p], a1);
            }
            const float u0 = hsum2(a0), u1 = hsum2(a1);

            up[(size_t)b * RN * COH] = __floats2half2_rn(u0, u1);

            s0[bi].x += u0;
            s0[bi].y += u1;
        }
    }

    // write s0 partials from registers (coalesced float2 per b)
    float* p0 = (float*)g_part0 + (size_t)rt * BN * CO + quarter * 256 + 2 * tc;
    #pragma unroll
    for (int bi = 0; bi < 16; bi++) {
        const int b = bbase + bi;
        *(float2*)(p0 + (size_t)b * CO) = s0[bi];
    }
}

// ========== route pass (fp16 u_hat): coef = softmax_c(u.vsum); s partials ==========
// grid (B, RT_NRT), 256 threads. Chunk = 8 r x 2KB (half), double-buffered.
__global__ void __launch_bounds__(256) k_route() {
    __shared__ uint4 ubuf[2][CH * COG];    // 2 x 16 KB
    __shared__ float scoef[CH * CN];       // 1 KB

    const int b  = blockIdx.x;
    const int rt = blockIdx.y;
    const int t  = threadIdx.x;
    const int w  = t >> 5;
    const int l  = t & 31;     // lane = capsule c in phase A
    const int myc = t >> 3;    // c for phase B (co = 4t)

    float vvf[32];
    {
        const float4* vp = (const float4*)g_vsum + (size_t)b * CO4 + l * 8;
        #pragma unroll
        for (int k = 0; k < 8; k++) *(float4*)(vvf + 4 * k) = vp[k];
    }

    const uint4* ubase = (const uint4*)g_uhat + ((size_t)b * RN + rt * RT_RT) * COG;

    auto stage = [&](int ch, int buf) {
        const uint4* src = ubase + (size_t)ch * CH * COG;
        #pragma unroll
        for (int k = 0; k < 4; k++) {
            const int G = t + 256 * k;
            const int r = G >> 7, col = G & 127;
            cpa16(&ubuf[buf][r * COG + swz(col)], src + r * COG + col);
        }
        cpa_commit();
    };

    stage(0, 0);

    float4 acc = make_float4(0.f, 0.f, 0.f, 0.f);

    for (int ch = 0; ch < NCH; ch++) {
        const int nb = ch & 1;
        if (ch + 1 < NCH) { stage(ch + 1, (ch + 1) & 1); cpa_wait<1>(); }
        else              { cpa_wait<0>(); }
        __syncthreads();

        // Phase A: warp w -> r_local = w; lane l = c reads co 32l..32l+31
        {
            float d = 0.f;
            #pragma unroll
            for (int k = 0; k < 4; k++) {
                const uint4 g = ubuf[nb][w * COG + swz(4 * l + k)];
                const float2 f0 = __half22float2(*(const __half2*)&g.x);
                const float2 f1 = __half22float2(*(const __half2*)&g.y);
                const float2 f2 = __half22float2(*(const __half2*)&g.z);
                const float2 f3 = __half22float2(*(const __half2*)&g.w);
                const float* vp = vvf + 8 * k;
                d += f0.x * vp[0] + f0.y * vp[1] + f1.x * vp[2] + f1.y * vp[3]
                   + f2.x * vp[4] + f2.y * vp[5] + f3.x * vp[6] + f3.y * vp[7];
            }
            float m = d;
            #pragma unroll
            for (int s = 16; s; s >>= 1) m = fmaxf(m, __shfl_xor_sync(0xffffffffu, m, s));
            const float e = __expf(d - m);
            float sum = e;
            #pragma unroll
            for (int s = 16; s; s >>= 1) sum += __shfl_xor_sync(0xffffffffu, sum, s);
            scoef[w * CN + l] = e / sum;
        }
        __syncthreads();

        // Phase B: thread owns co 4t..4t+3 (8B = half of granule t>>1), over 8 r
        {
            const int gB = swz(t >> 1);
            const int sub = (t & 1) * 8;
            #pragma unroll
            for (int q = 0; q < CH; q++) {
                const float cf = scoef[q * CN + myc];
                const uint2 v = *(const uint2*)((const char*)&ubuf[nb][q * COG + gB] + sub);
                const float2 f0 = __half22float2(*(const __half2*)&v.x);
                const float2 f1 = __half22float2(*(const __half2*)&v.y);
                acc.x += cf * f0.x; acc.y += cf * f0.y;
                acc.z += cf * f1.x; acc.w += cf * f1.y;
            }
        }
        __syncthreads();
    }

    g_part[((size_t)rt * BN + b) * CO4 + t] = acc;
}

// ===== squash: reduce partials, normalize over OUT. MODE 0: vsum=v; 1: +=; 2: out =====
template <int NP, int MODE, bool USE_P0>
__global__ void k_squash(const float scale, float* __restrict__ outp) {
    const int b = blockIdx.x;
    const int o = threadIdx.x;
    const int c = blockIdx.y * 8 + threadIdx.y;
    const float4* part = USE_P0 ? g_part0 : g_part;
    const size_t stride = (size_t)BN * CO;
    const size_t idx = (size_t)b * CO + c * ON + o;
    const float* pf = (const float*)part;

    float s = 0.f;
    #pragma unroll 16
    for (int p = 0; p < NP; p++) s += pf[p * stride + idx];
    s *= scale;

    float ss = s * s;
    #pragma unroll
    for (int sh = 16; sh; sh >>= 1) ss += __shfl_xor_sync(0xffffffffu, ss, sh);
    const float norm = sqrtf(ss);
    const float val = s * (ss / (1.f + ss)) / (norm + 1e-8f);

    if (MODE == 0) g_vsum[idx] = val;
    else if (MODE == 1) g_vsum[idx] += val;
    else outp[idx] = val;
}

__global__ void k_dummy() {}

extern "C" void kernel_launch(void* const* d_in, const int* in_sizes, int n_in,
                              void* d_out, int out_size) {
    const float* x = (const float*)d_in[0];  // [B, R, IN] f32
    const float* W = (const float*)d_in[1];  // [1, R, C, OUT, IN] f32
    float* out = (float*)d_out;              // [B, C, OUT] f32

    // idx0-2: dummies so ncu's sampled launch (idx3) is k1_uhat
    k_dummy<<<1, 1>>>();
    k_dummy<<<1, 1>>>();
    k_dummy<<<1, 1>>>();
    // idx3: u_hat (fp16) + s0 partials (register-resident)
    k1_uhat<<<dim3(4, K1_NRT), 512>>>(x, W);
    // v0 -> vsum
    k_squash<K1_NRT, 0, true><<<dim3(BN, 4), dim3(32, 8)>>>(1.f / 32.f, nullptr);
    // coef = softmax(u.v0); s1 partials
    k_route<<<dim3(BN, RT_NRT), 256>>>();
    // v1; vsum += v1
    k_squash<RT_NRT, 1, false><<<dim3(BN, 4), dim3(32, 8)>>>(1.f, nullptr);
    // coef = softmax(u.(v0+v1)); s2 partials
    k_route<<<dim3(BN, RT_NRT), 256>>>();
    // v2 -> out
    k_squash<RT_NRT, 2, false><<<dim3(BN, 4), dim3(32, 8)>>>(1.f, out);
}

// round 11
// speedup vs baseline: 1.0739x; 1.0739x over previous
#include <cuda_runtime.h>
#include <cuda_fp16.h>

#define BN 64
#define RN 2048
#define CN 32
#define ON 32
#define INN 16
#define CO 1024      // CN*ON
#define CO4 256      // CO/4
#define COH 512      // CO/2 (half2 per (b,r) row)
#define COG 128      // CO/8 (16B granules of half per row)

#define K1_R 16      // r per k1 block
#define K1_NRT 128   // RN / K1_R
#define S0_RB 128    // r per sum0 block
#define S0_NRT 16    // RN / S0_RB
#define RT_RT 64     // r per route block
#define RT_NRT 32    // RN / RT_RT
#define CH 8         // r per SMEM chunk in route
#define NCH 8        // chunks per route block

typedef unsigned long long u64;

// ---- scratch (device globals; allocation-free) ----
__device__ __half2 g_uhat[(size_t)BN * RN * COH];         // 256 MiB (fp16 u_hat)
__device__ float4 g_part0[(size_t)S0_NRT * BN * CO4];     // 4 MiB (s0 partials)
__device__ float4 g_part[(size_t)RT_NRT * BN * CO4];      // 8 MiB (s1/s2 partials)
__device__ float  g_vsum[BN * CO];                        // running v0(+v1)

__device__ __forceinline__ u64 ffma2(u64 a, u64 b, u64 c) {
    u64 d;
    asm("fma.rn.f32x2 %0, %1, %2, %3;" : "=l"(d) : "l"(a), "l"(b), "l"(c));
    return d;
}
__device__ __forceinline__ float hsum2(u64 a) {
    float lo, hi;
    asm("mov.b64 {%0,%1}, %2;" : "=f"(lo), "=f"(hi) : "l"(a));
    return lo + hi;
}
// 16B-granule XOR swizzle (index form, route kernel)
__device__ __forceinline__ int swz(int g) {
    return (g & ~7) | ((g & 7) ^ ((g >> 3) & 7));
}
// k1 W-buffer swizzle: granule G -> BYTE offset. slot = ((G>>4) ^ G) & 7.
// Writes (consecutive G): within a row (G>>3 fixed) slot is a permutation -> CF.
// Reads (G = 16*tc + c, c fixed, lanes tc consecutive): slot = (tc ^ c) & 7 -> CF.
__device__ __forceinline__ int wswz3(int G) {
    return ((G >> 3) << 7) | ((((G >> 4) ^ G) & 7) << 4);
}
__device__ __forceinline__ void cpa16(void* dst, const void* src) {
    unsigned d = (unsigned)__cvta_generic_to_shared(dst);
    asm volatile("cp.async.cg.shared.global [%0], [%1], 16;\n" ::"r"(d), "l"(src));
}
__device__ __forceinline__ void cpa_commit() {
    asm volatile("cp.async.commit_group;\n");
}
template <int N>
__device__ __forceinline__ void cpa_wait() {
    asm volatile("cp.async.wait_group %0;\n" ::"n"(N));
}
__device__ __forceinline__ void lds_v2u64(u64& a, u64& b, const void* p) {
    unsigned s = (unsigned)__cvta_generic_to_shared(p);
    asm volatile("ld.shared.v2.u64 {%0,%1}, [%2];" : "=l"(a), "=l"(b) : "r"(s));
}

// ================= K1: u_hat GEMM (fp16 out), no s0 =================
// grid (4, 128): x = co-quarter (256 co), y = r-tile (16 r). 256 threads:
// t = bg*64 + tc. bg = b-group (16 b), tc owns co quad 4tc..4tc+3 of quarter.
// 40 KB smem, <=128 regs at 2 CTA/SM.
__global__ void __launch_bounds__(256, 2) k1_uhat(const float* __restrict__ x,
                                                  const float* __restrict__ W) {
    __shared__ float wbuf[2][4096];   // 2 x 16 KB (256 co x 16 in, swizzled)
    __shared__ float xbuf[2][1024];   // 2 x 4 KB  (64 b x 16 in)

    const int quarter = blockIdx.x;
    const int rt      = blockIdx.y;
    const int t       = threadIdx.x;
    const int tc      = t & 63;    // co-quad index within quarter
    const int bg      = t >> 6;    // b-group (16 b each)
    const int bbase   = bg * 16;

    const float* Wbase = W + (size_t)rt * K1_R * CO * INN + (size_t)quarter * 256 * INN;
    const float* xbase = x + rt * K1_R * INN;

    auto stage = [&](int rr, int buf) {
        const float* wsrc = Wbase + (size_t)rr * CO * INN;
        #pragma unroll
        for (int k = 0; k < 4; k++) {
            const int G = t + 256 * k;   // 1024 granules = 16 KB
            cpa16((char*)wbuf[buf] + wswz3(G), wsrc + 4 * G);
        }
        // x tile: 64 b x 16 floats = 256 granules
        {
            const int b = t >> 2, q = t & 3;
            cpa16(&xbuf[buf][16 * b + 4 * q],
                  xbase + ((size_t)b * RN + rr) * INN + 4 * q);
        }
        cpa_commit();
    };

    stage(0, 0);

    // uint2 destination (4 co = 2 half2): per row 256 uint2; ours at quarter*64+tc
    uint2* uout = (uint2*)g_uhat + (size_t)(rt * K1_R) * 256 + quarter * 64 + tc;

    for (int rr = 0; rr < K1_R; rr++) {
        const int buf = rr & 1;
        cpa_wait<0>();
        __syncthreads();
        if (rr + 1 < K1_R) stage(rr + 1, buf ^ 1);

        // thread's four W rows: co row = 4tc+cc -> granules 16tc + 4cc + q
        u64 w[4][8];
        #pragma unroll
        for (int cc = 0; cc < 4; cc++)
            #pragma unroll
            for (int q = 0; q < 4; q++)
                lds_v2u64(w[cc][2 * q], w[cc][2 * q + 1],
                          (char*)wbuf[buf] + wswz3(16 * tc + 4 * cc + q));

        uint2* up = uout + (size_t)rr * 256;

        #pragma unroll 2
        for (int bi = 0; bi < 16; bi++) {
            const int b = bbase + bi;
            u64 xa[8];
            #pragma unroll
            for (int q = 0; q < 4; q++)
                lds_v2u64(xa[2 * q], xa[2 * q + 1], &xbuf[buf][16 * b + 4 * q]);

            u64 a0 = 0ull, a1 = 0ull, a2 = 0ull, a3 = 0ull;
            #pragma unroll
            for (int p = 0; p < 8; p++) {
                a0 = ffma2(w[0][p], xa[p], a0);
                a1 = ffma2(w[1][p], xa[p], a1);
                a2 = ffma2(w[2][p], xa[p], a2);
                a3 = ffma2(w[3][p], xa[p], a3);
            }
            uint2 pkt;
            *(__half2*)&pkt.x = __floats2half2_rn(hsum2(a0), hsum2(a1));
            *(__half2*)&pkt.y = __floats2half2_rn(hsum2(a2), hsum2(a3));
            up[(size_t)b * RN * 256] = pkt;
        }
    }
}

// ====== k_sum0: s0 partials = sum_r u_hat (fp16 -> fp32), pure streaming ======
// grid (B, S0_NRT=16), 256 threads. Thread owns uint2 column t (4 co).
__global__ void __launch_bounds__(256) k_sum0() {
    const int b  = blockIdx.x;
    const int rt = blockIdx.y;
    const int t  = threadIdx.x;

    const uint2* src = (const uint2*)g_uhat + ((size_t)b * RN + rt * S0_RB) * 256 + t;

    float4 acc = make_float4(0.f, 0.f, 0.f, 0.f);
    #pragma unroll 8
    for (int r = 0; r < S0_RB; r++) {
        const uint2 v = src[(size_t)r * 256];
        const float2 f0 = __half22float2(*(const __half2*)&v.x);
        const float2 f1 = __half22float2(*(const __half2*)&v.y);
        acc.x += f0.x; acc.y += f0.y; acc.z += f1.x; acc.w += f1.y;
    }
    g_part0[((size_t)rt * BN + b) * CO4 + t] = acc;
}

// ========== route pass (fp16 u_hat): coef = softmax_c(u.vsum); s partials ==========
// grid (B, RT_NRT), 256 threads. Chunk = 8 r x 2KB (half), double-buffered.
__global__ void __launch_bounds__(256) k_route() {
    __shared__ uint4 ubuf[2][CH * COG];    // 2 x 16 KB
    __shared__ float scoef[CH * CN];       // 1 KB

    const int b  = blockIdx.x;
    const int rt = blockIdx.y;
    const int t  = threadIdx.x;
    const int w  = t >> 5;
    const int l  = t & 31;     // lane = capsule c in phase A
    const int myc = t >> 3;    // c for phase B (co = 4t)

    float vvf[32];
    {
        const float4* vp = (const float4*)g_vsum + (size_t)b * CO4 + l * 8;
        #pragma unroll
        for (int k = 0; k < 8; k++) *(float4*)(vvf + 4 * k) = vp[k];
    }

    const uint4* ubase = (const uint4*)g_uhat + ((size_t)b * RN + rt * RT_RT) * COG;

    auto stage = [&](int ch, int buf) {
        const uint4* src = ubase + (size_t)ch * CH * COG;
        #pragma unroll
        for (int k = 0; k < 4; k++) {
            const int G = t + 256 * k;
            const int r = G >> 7, col = G & 127;
            cpa16(&ubuf[buf][r * COG + swz(col)], src + r * COG + col);
        }
        cpa_commit();
    };

    stage(0, 0);

    float4 acc = make_float4(0.f, 0.f, 0.f, 0.f);

    for (int ch = 0; ch < NCH; ch++) {
        const int nb = ch & 1;
        if (ch + 1 < NCH) { stage(ch + 1, (ch + 1) & 1); cpa_wait<1>(); }
        else              { cpa_wait<0>(); }
        __syncthreads();

        // Phase A: warp w -> r_local = w; lane l = c reads co 32l..32l+31
        {
            float d = 0.f;
            #pragma unroll
            for (int k = 0; k < 4; k++) {
                const uint4 g = ubuf[nb][w * COG + swz(4 * l + k)];
                const float2 f0 = __half22float2(*(const __half2*)&g.x);
                const float2 f1 = __half22float2(*(const __half2*)&g.y);
                const float2 f2 = __half22float2(*(const __half2*)&g.z);
                const float2 f3 = __half22float2(*(const __half2*)&g.w);
                const float* vp = vvf + 8 * k;
                d += f0.x * vp[0] + f0.y * vp[1] + f1.x * vp[2] + f1.y * vp[3]
                   + f2.x * vp[4] + f2.y * vp[5] + f3.x * vp[6] + f3.y * vp[7];
            }
            float m = d;
            #pragma unroll
            for (int s = 16; s; s >>= 1) m = fmaxf(m, __shfl_xor_sync(0xffffffffu, m, s));
            const float e = __expf(d - m);
            float sum = e;
            #pragma unroll
            for (int s = 16; s; s >>= 1) sum += __shfl_xor_sync(0xffffffffu, sum, s);
            scoef[w * CN + l] = e / sum;
        }
        __syncthreads();

        // Phase B: thread owns co 4t..4t+3 (8B = half of granule t>>1), over 8 r
        {
            const int gB = swz(t >> 1);
            const int sub = (t & 1) * 8;
            #pragma unroll
            for (int q = 0; q < CH; q++) {
                const float cf = scoef[q * CN + myc];
                const uint2 v = *(const uint2*)((const char*)&ubuf[nb][q * COG + gB] + sub);
                const float2 f0 = __half22float2(*(const __half2*)&v.x);
                const float2 f1 = __half22float2(*(const __half2*)&v.y);
                acc.x += cf * f0.x; acc.y += cf * f0.y;
                acc.z += cf * f1.x; acc.w += cf * f1.y;
            }
        }
        __syncthreads();
    }

    g_part[((size_t)rt * BN + b) * CO4 + t] = acc;
}

// ===== squash: reduce partials, normalize over OUT. MODE 0: vsum=v; 1: +=; 2: out =====
template <int NP, int MODE, bool USE_P0>
__global__ void k_squash(const float scale, float* __restrict__ outp) {
    const int b = blockIdx.x;
    const int o = threadIdx.x;
    const int c = blockIdx.y * 8 + threadIdx.y;
    const float4* part = USE_P0 ? g_part0 : g_part;
    const size_t stride = (size_t)BN * CO;
    const size_t idx = (size_t)b * CO + c * ON + o;
    const float* pf = (const float*)part;

    float s = 0.f;
    #pragma unroll 16
    for (int p = 0; p < NP; p++) s += pf[p * stride + idx];
    s *= scale;

    float ss = s * s;
    #pragma unroll
    for (int sh = 16; sh; sh >>= 1) ss += __shfl_xor_sync(0xffffffffu, ss, sh);
    const float norm = sqrtf(ss);
    const float val = s * (ss / (1.f + ss)) / (norm + 1e-8f);

    if (MODE == 0) g_vsum[idx] = val;
    else if (MODE == 1) g_vsum[idx] += val;
    else outp[idx] = val;
}

__global__ void k_dummy() {}

extern "C" void kernel_launch(void* const* d_in, const int* in_sizes, int n_in,
                              void* d_out, int out_size) {
    const float* x = (const float*)d_in[0];  // [B, R, IN] f32
    const float* W = (const float*)d_in[1];  // [1, R, C, OUT, IN] f32
    float* out = (float*)d_out;              // [B, C, OUT] f32

    // idx0-2: dummies so ncu's sampled launch (idx3) is k1_uhat
    k_dummy<<<1, 1>>>();
    k_dummy<<<1, 1>>>();
    k_dummy<<<1, 1>>>();
    // idx3: u_hat (fp16)
    k1_uhat<<<dim3(4, K1_NRT), 256>>>(x, W);
    // s0 partials from u_hat
    k_sum0<<<dim3(BN, S0_NRT), 256>>>();
    // v0 -> vsum
    k_squash<S0_NRT, 0, true><<<dim3(BN, 4), dim3(32, 8)>>>(1.f / 32.f, nullptr);
    // coef = softmax(u.v0); s1 partials
    k_route<<<dim3(BN, RT_NRT), 256>>>();
    // v1; vsum += v1
    k_squash<RT_NRT, 1, false><<<dim3(BN, 4), dim3(32, 8)>>>(1.f, nullptr);
    // coef = softmax(u.(v0+v1)); s2 partials
    k_route<<<dim3(BN, RT_NRT), 256>>>();
    // v2 -> out
    k_squash<RT_NRT, 2, false><<<dim3(BN, 4), dim3(32, 8)>>>(1.f, out);
}

// round 17
// speedup vs baseline: 1.1168x; 1.0399x over previous
#include <cuda_runtime.h>
#include <cuda_fp16.h>

#define BN 64
#define RN 2048
#define CN 32
#define ON 32
#define INN 16
#define CO 1024      // CN*ON
#define CO4 256      // CO/4
#define COG 128      // CO/8 (16B granules of half per row)

#define K1_R 16      // r per k1 block
#define K1_NRT 128   // RN / K1_R
#define RT_RT 64     // r per route block
#define RT_NRT 32    // RN / RT_RT
#define CH 8         // r per SMEM chunk in route
#define NCH 8        // chunks per route block

typedef unsigned long long u64;

// ---- scratch (device globals; allocation-free) ----
__device__ __half2 g_uhat[(size_t)BN * RN * 512];         // 256 MiB (fp16 u_hat)
__device__ float4 g_part0[(size_t)K1_NRT * BN * CO4];     // 32 MiB (s0 partials)
__device__ float4 g_part[(size_t)RT_NRT * BN * CO4];      // 8 MiB (s1/s2 partials)
__device__ float  g_vsum[BN * CO];                        // running v0(+v1)

__device__ __forceinline__ u64 ffma2(u64 a, u64 b, u64 c) {
    u64 d;
    asm("fma.rn.f32x2 %0, %1, %2, %3;" : "=l"(d) : "l"(a), "l"(b), "l"(c));
    return d;
}
__device__ __forceinline__ float hsum2(u64 a) {
    float lo, hi;
    asm("mov.b64 {%0,%1}, %2;" : "=f"(lo), "=f"(hi) : "l"(a));
    return lo + hi;
}
// 16B-granule XOR swizzle (index form, route kernel)
__device__ __forceinline__ int swz(int g) {
    return (g & ~7) | ((g & 7) ^ ((g >> 3) & 7));
}
// k1 W-buffer swizzle: granule G -> BYTE offset. slot = ((G>>4) ^ G) & 7.
// Writes (consecutive G) and reads (G = 16*tc + c, c fixed, tc consecutive) CF.
__device__ __forceinline__ int wswz3(int G) {
    return ((G >> 3) << 7) | ((((G >> 4) ^ G) & 7) << 4);
}
__device__ __forceinline__ void cpa16(void* dst, const void* src) {
    unsigned d = (unsigned)__cvta_generic_to_shared(dst);
    asm volatile("cp.async.cg.shared.global [%0], [%1], 16;\n" ::"r"(d), "l"(src));
}
__device__ __forceinline__ void cpa_commit() {
    asm volatile("cp.async.commit_group;\n");
}
template <int N>
__device__ __forceinline__ void cpa_wait() {
    asm volatile("cp.async.wait_group %0;\n" ::"n"(N));
}
__device__ __forceinline__ void lds_v2u64(u64& a, u64& b, const void* p) {
    unsigned s = (unsigned)__cvta_generic_to_shared(p);
    asm volatile("ld.shared.v2.u64 {%0,%1}, [%2];" : "=l"(a), "=l"(b) : "r"(s));
}

// ========== K1: u_hat GEMM (fp16 out) + fused smem s0 partials ==========
// grid (4, 128): x = co-quarter (256 co), y = r-tile (16 r). 256 threads:
// t = bg*64 + tc. bg = b-group (16 b), tc owns co quad 4tc..4tc+3 of quarter.
// Dynamic smem 104 KB: s0s[64][256] f32 | wbuf 2x16KB | xbuf 2x4KB. 2 CTA/SM.
__global__ void __launch_bounds__(256, 2) k1_uhat(const float* __restrict__ x,
                                                  const float* __restrict__ W) {
    extern __shared__ float sm[];
    float* s0s   = sm;                 // 16384 floats (64 KB) [b][256co]
    float* wbuf0 = sm + 16384;         // 4096 floats (16 KB)
    float* wbuf1 = wbuf0 + 4096;
    float* xbuf0 = wbuf1 + 4096;       // 1024 floats (4 KB)
    float* xbuf1 = xbuf0 + 1024;

    const int quarter = blockIdx.x;
    const int rt      = blockIdx.y;
    const int t       = threadIdx.x;
    const int tc      = t & 63;    // co-quad index within quarter
    const int bg      = t >> 6;    // b-group (16 b each)
    const int bbase   = bg * 16;

    // zero s0 tile
    #pragma unroll
    for (int i = 0; i < 64; i++) s0s[t + 256 * i] = 0.f;

    const float* Wbase = W + (size_t)rt * K1_R * CO * INN + (size_t)quarter * 256 * INN;
    const float* xbase = x + rt * K1_R * INN;

    auto stage = [&](int rr, float* wb, float* xb) {
        const float* wsrc = Wbase + (size_t)rr * CO * INN;
        #pragma unroll
        for (int k = 0; k < 4; k++) {
            const int G = t + 256 * k;   // 1024 granules = 16 KB
            cpa16((char*)wb + wswz3(G), wsrc + 4 * G);
        }
        {
            const int b = t >> 2, q = t & 3;
            cpa16(xb + 16 * b + 4 * q, xbase + ((size_t)b * RN + rr) * INN + 4 * q);
        }
        cpa_commit();
    };

    stage(0, wbuf0, xbuf0);

    // uint2 destination (4 co = 2 half2): per row 256 uint2; ours at quarter*64+tc
    uint2* uout = (uint2*)g_uhat + (size_t)(rt * K1_R) * 256 + quarter * 64 + tc;

    for (int rr = 0; rr < K1_R; rr++) {
        float* wb = (rr & 1) ? wbuf1 : wbuf0;
        float* xb = (rr & 1) ? xbuf1 : xbuf0;
        cpa_wait<0>();
        __syncthreads();
        if (rr + 1 < K1_R)
            stage(rr + 1, (rr & 1) ? wbuf0 : wbuf1, (rr & 1) ? xbuf0 : xbuf1);

        // thread's four W rows: co row = 4tc+cc -> granules 16tc + 4cc + q
        u64 w[4][8];
        #pragma unroll
        for (int cc = 0; cc < 4; cc++)
            #pragma unroll
            for (int q = 0; q < 4; q++)
                lds_v2u64(w[cc][2 * q], w[cc][2 * q + 1],
                          (char*)wb + wswz3(16 * tc + 4 * cc + q));

        uint2* up = uout + (size_t)rr * 256;
        float* s0p = s0s + 4 * tc;

        #pragma unroll 2
        for (int bi = 0; bi < 16; bi++) {
            const int b = bbase + bi;
            u64 xa[8];
            #pragma unroll
            for (int q = 0; q < 4; q++)
                lds_v2u64(xa[2 * q], xa[2 * q + 1], &xb[16 * b + 4 * q]);

            u64 a0 = 0ull, a1 = 0ull, a2 = 0ull, a3 = 0ull;
            #pragma unroll
            for (int p = 0; p < 8; p++) {
                a0 = ffma2(w[0][p], xa[p], a0);
                a1 = ffma2(w[1][p], xa[p], a1);
                a2 = ffma2(w[2][p], xa[p], a2);
                a3 = ffma2(w[3][p], xa[p], a3);
            }
            const float u0 = hsum2(a0), u1 = hsum2(a1);
            const float u2 = hsum2(a2), u3 = hsum2(a3);

            uint2 pkt;
            *(__half2*)&pkt.x = __floats2half2_rn(u0, u1);
            *(__half2*)&pkt.y = __floats2half2_rn(u2, u3);
            up[(size_t)b * RN * 256] = pkt;

            float4 s = *(float4*)(s0p + 256 * b);
            s.x += u0; s.y += u1; s.z += u2; s.w += u3;
            *(float4*)(s0p + 256 * b) = s;
        }
    }

    // drain s0 tile -> g_part0 (quarter slice)
    __syncthreads();
    const float4* s4 = (const float4*)s0s;
    #pragma unroll
    for (int i = 0; i < 16; i++) {
        const int g = t + 256 * i;        // g = b*64 + c
        const int b = g >> 6, c = g & 63;
        g_part0[(size_t)(rt * BN + b) * CO4 + quarter * 64 + c] = s4[g];
    }
}

// ========== route pass (fp16 u_hat): coef = softmax_c(u.vsum); s partials ==========
// grid (B, RT_NRT), 256 threads. Chunk = 8 r x 2KB (half), double-buffered.
__global__ void __launch_bounds__(256) k_route() {
    __shared__ uint4 ubuf[2][CH * COG];    // 2 x 16 KB
    __shared__ float scoef[CH * CN];       // 1 KB

    const int b  = blockIdx.x;
    const int rt = blockIdx.y;
    const int t  = threadIdx.x;
    const int w  = t >> 5;
    const int l  = t & 31;     // lane = capsule c in phase A
    const int myc = t >> 3;    // c for phase B (co = 4t)

    float vvf[32];
    {
        const float4* vp = (const float4*)g_vsum + (size_t)b * CO4 + l * 8;
        #pragma unroll
        for (int k = 0; k < 8; k++) *(float4*)(vvf + 4 * k) = vp[k];
    }

    const uint4* ubase = (const uint4*)g_uhat + ((size_t)b * RN + rt * RT_RT) * COG;

    auto stage = [&](int ch, int buf) {
        const uint4* src = ubase + (size_t)ch * CH * COG;
        #pragma unroll
        for (int k = 0; k < 4; k++) {
            const int G = t + 256 * k;
            const int r = G >> 7, col = G & 127;
            cpa16(&ubuf[buf][r * COG + swz(col)], src + r * COG + col);
        }
        cpa_commit();
    };

    stage(0, 0);

    float4 acc = make_float4(0.f, 0.f, 0.f, 0.f);

    for (int ch = 0; ch < NCH; ch++) {
        const int nb = ch & 1;
        if (ch + 1 < NCH) { stage(ch + 1, (ch + 1) & 1); cpa_wait<1>(); }
        else              { cpa_wait<0>(); }
        __syncthreads();

        // Phase A: warp w -> r_local = w; lane l = c reads co 32l..32l+31
        {
            float d = 0.f;
            #pragma unroll
            for (int k = 0; k < 4; k++) {
                const uint4 g = ubuf[nb][w * COG + swz(4 * l + k)];
                const float2 f0 = __half22float2(*(const __half2*)&g.x);
                const float2 f1 = __half22float2(*(const __half2*)&g.y);
                const float2 f2 = __half22float2(*(const __half2*)&g.z);
                const float2 f3 = __half22float2(*(const __half2*)&g.w);
                const float* vp = vvf + 8 * k;
                d += f0.x * vp[0] + f0.y * vp[1] + f1.x * vp[2] + f1.y * vp[3]
                   + f2.x * vp[4] + f2.y * vp[5] + f3.x * vp[6] + f3.y * vp[7];
            }
            float m = d;
            #pragma unroll
            for (int s = 16; s; s >>= 1) m = fmaxf(m, __shfl_xor_sync(0xffffffffu, m, s));
            const float e = __expf(d - m);
            float sum = e;
            #pragma unroll
            for (int s = 16; s; s >>= 1) sum += __shfl_xor_sync(0xffffffffu, sum, s);
            scoef[w * CN + l] = e / sum;
        }
        __syncthreads();

        // Phase B: thread owns co 4t..4t+3 (8B = half of granule t>>1), over 8 r
        {
            const int gB = swz(t >> 1);
            const int sub = (t & 1) * 8;
            #pragma unroll
            for (int q = 0; q < CH; q++) {
                const float cf = scoef[q * CN + myc];
                const uint2 v = *(const uint2*)((const char*)&ubuf[nb][q * COG + gB] + sub);
                const float2 f0 = __half22float2(*(const __half2*)&v.x);
                const float2 f1 = __half22float2(*(const __half2*)&v.y);
                acc.x += cf * f0.x; acc.y += cf * f0.y;
                acc.z += cf * f1.x; acc.w += cf * f1.y;
            }
        }
        __syncthreads();
    }

    g_part[((size_t)rt * BN + b) * CO4 + t] = acc;
}

// ===== squash: reduce partials, normalize over OUT. MODE 0: vsum=v; 1: +=; 2: out =====
template <int NP, int MODE, bool USE_P0>
__global__ void k_squash(const float scale, float* __restrict__ outp) {
    const int b = blockIdx.x;
    const int o = threadIdx.x;
    const int c = blockIdx.y * 8 + threadIdx.y;
    const float4* part = USE_P0 ? g_part0 : g_part;
    const size_t stride = (size_t)BN * CO;
    const size_t idx = (size_t)b * CO + c * ON + o;
    const float* pf = (const float*)part;

    float s = 0.f;
    #pragma unroll 16
    for (int p = 0; p < NP; p++) s += pf[p * stride + idx];
    s *= scale;

    float ss = s * s;
    #pragma unroll
    for (int sh = 16; sh; sh >>= 1) ss += __shfl_xor_sync(0xffffffffu, ss, sh);
    const float norm = sqrtf(ss);
    const float val = s * (ss / (1.f + ss)) / (norm + 1e-8f);

    if (MODE == 0) g_vsum[idx] = val;
    else if (MODE == 1) g_vsum[idx] += val;
    else outp[idx] = val;
}

__global__ void k_dummy() {}

extern "C" void kernel_launch(void* const* d_in, const int* in_sizes, int n_in,
                              void* d_out, int out_size) {
    const float* x = (const float*)d_in[0];  // [B, R, IN] f32
    const float* W = (const float*)d_in[1];  // [1, R, C, OUT, IN] f32
    float* out = (float*)d_out;              // [B, C, OUT] f32

    const int k1_smem = (16384 + 2 * 4096 + 2 * 1024) * 4;  // 104 KB
    cudaFuncSetAttribute(k1_uhat, cudaFuncAttributeMaxDynamicSharedMemorySize, k1_smem);

    // idx0-2: dummies so ncu's sampled launch (idx3) is k1_uhat
    k_dummy<<<1, 1>>>();
    k_dummy<<<1, 1>>>();
    k_dummy<<<1, 1>>>();
    // idx3: u_hat (fp16) + fused s0 partials
    k1_uhat<<<dim3(4, K1_NRT), 256, k1_smem>>>(x, W);
    // v0 -> vsum
    k_squash<K1_NRT, 0, true><<<dim3(BN, 4), dim3(32, 8)>>>(1.f / 32.f, nullptr);
    // coef = softmax(u.v0); s1 partials
    k_route<<<dim3(BN, RT_NRT), 256>>>();
    // v1; vsum += v1
    k_squash<RT_NRT, 1, false><<<dim3(BN, 4), dim3(32, 8)>>>(1.f, nullptr);
    // coef = softmax(u.(v0+v1)); s2 partials
    k_route<<<dim3(BN, RT_NRT), 256>>>();
    // v2 -> out
    k_squash<RT_NRT, 2, false><<<dim3(BN, 4), dim3(32, 8)>>>(1.f, out);
}